// round 16
// baseline (speedup 1.0000x reference)
#include <cuda_runtime.h>
#include <cstdint>

#define N_PAIRS 64000
#define N_ATOMS 16000
#define NF 8
#define NH 100
#define KDIM 900            // (NF+1)*NH
#define NPAD 128            // padded cols (100 real + 28 zero)
#define BM 112              // rows per CTA -> 143 CTAs, single wave
#define GRID ((N_ATOMS + BM - 1) / BM)   // 143
#define BK 36               // K chunk (18 k-pairs); 25 iters
#define NITER 25
#define THREADS 512         // 16 warps; warp w rows [7w,7w+7), lane l cols [4l,4l+4)
#define RPW 7               // rows per warp
#define MAX_DEG 48
#define NSTAGE 3

#define SROW_B 144                    // 36 floats * 4 B per S tile row
#define SS_STAGE (BM * SROW_B)        // 16128 B
#define WS_STAGE (BK / 2 * NPAD * 8)  // 18432 B : 18 kpairs x 128 float2
#define SMEM_TOTAL (NSTAGE * (SS_STAGE + WS_STAGE))   // 103680 B

// ---------------------------------------------------------------------------
// Scratch (static device globals; no runtime allocation allowed)
// ---------------------------------------------------------------------------
__device__ float    g_S[(size_t)N_ATOMS * KDIM];        // 57.6 MB, [atom][900]
__device__ float    g_Wp[(size_t)(KDIM / 2) * NPAD * 2];// [kpair][col] float2
__device__ uint32_t g_cursor[N_ATOMS];
__device__ uint32_t g_elist[(size_t)N_ATOMS * MAX_DEG];

__device__ __forceinline__ uint32_t smem_u32(const void* p) {
    uint32_t a;
    asm("{ .reg .u64 t; cvta.to.shared.u64 t, %1; cvt.u32.u64 %0, t; }" : "=r"(a) : "l"(p));
    return a;
}

// ---------------------------------------------------------------------------
// prep: g_Wp[kp*128 + n] = (Wt[2kp][n], Wt[2kp+1][n])
// Wt[k][n]: k=f*100+j; f<8 -> W[f, n*100+j]; f==8 -> b[n*100+j]; pad n>=100 -> 0
// ---------------------------------------------------------------------------
__device__ __forceinline__ float wt_elem(const float* W, const float* b, int k, int n) {
    if (n >= NH) return 0.f;
    int f = k / NH;
    int j = k - f * NH;
    return (f < NF) ? W[f * (NH * NH) + n * NH + j] : b[n * NH + j];
}

__global__ void prep_wp_kernel(const float* __restrict__ W, const float* __restrict__ b) {
    int tid = blockIdx.x * blockDim.x + threadIdx.x;
    if (tid >= (KDIM / 2) * 32) return;
    int kp = tid >> 5;
    int q  = tid & 31;              // 4-col group
    int k0 = 2 * kp, k1 = 2 * kp + 1;
    float a0 = wt_elem(W, b, k0, q * 4 + 0), b0 = wt_elem(W, b, k1, q * 4 + 0);
    float a1 = wt_elem(W, b, k0, q * 4 + 1), b1 = wt_elem(W, b, k1, q * 4 + 1);
    float a2 = wt_elem(W, b, k0, q * 4 + 2), b2 = wt_elem(W, b, k1, q * 4 + 2);
    float a3 = wt_elem(W, b, k0, q * 4 + 3), b3 = wt_elem(W, b, k1, q * 4 + 3);
    float* dst = g_Wp + (size_t)kp * (NPAD * 2) + q * 8;
    *(float4*)(dst + 0) = make_float4(a0, b0, a1, b1);
    *(float4*)(dst + 4) = make_float4(a2, b2, a3, b3);
}

// ---------------------------------------------------------------------------
// Bucket fill: elist[dst][pos] = e  (cursor pre-zeroed)
// ---------------------------------------------------------------------------
__global__ void fill_kernel(const int* __restrict__ a2p) {
    int e = blockIdx.x * blockDim.x + threadIdx.x;
    if (e >= N_PAIRS) return;
    int dst = a2p[2 * e];
    uint32_t pos = atomicAdd(&g_cursor[dst], 1u);
    if (pos < MAX_DEG) g_elist[(size_t)dst * MAX_DEG + pos] = (uint32_t)e;
}

// ---------------------------------------------------------------------------
// Gather: thread = (atom a, q in [0,25)). S[a, f*100+q*4..+3] for 9 features.
// ---------------------------------------------------------------------------
__global__ void gather_kernel(const float* __restrict__ pf,
                              const float* __restrict__ af,
                              const int*   __restrict__ a2p) {
    int tid = threadIdx.x;                 // 0..249 (10 atoms per block)
    if (tid >= 250) return;
    int a = blockIdx.x * 10 + tid / 25;
    int q = tid % 25;

    int deg = (int)g_cursor[a];
    if (deg > MAX_DEG) deg = MAX_DEG;

    float acc[9][4];
#pragma unroll
    for (int f = 0; f < 9; f++)
#pragma unroll
        for (int i = 0; i < 4; i++) acc[f][i] = 0.f;

    const uint32_t* lst = g_elist + (size_t)a * MAX_DEG;
    for (int i = 0; i < deg; i++) {
        int e = (int)lst[i];
        int src = a2p[2 * e + 1];
        float4 v  = *(const float4*)(af + (size_t)src * NH + q * 4);
        float4 c0 = *(const float4*)(pf + (size_t)e * NF);
        float4 c1 = *(const float4*)(pf + (size_t)e * NF + 4);
        float coef[9] = {c0.x, c0.y, c0.z, c0.w, c1.x, c1.y, c1.z, c1.w, 1.0f};
#pragma unroll
        for (int f = 0; f < 9; f++) {
            acc[f][0] += coef[f] * v.x;
            acc[f][1] += coef[f] * v.y;
            acc[f][2] += coef[f] * v.z;
            acc[f][3] += coef[f] * v.w;
        }
    }

    float* base = g_S + (size_t)a * KDIM + q * 4;
#pragma unroll
    for (int f = 0; f < 9; f++)
        *(float4*)(base + f * NH) = make_float4(acc[f][0], acc[f][1], acc[f][2], acc[f][3]);
}

// ---------------------------------------------------------------------------
// GEMM: out[16000,100] = S[16000,900] @ Wt[900,128]
// Partial-sum-pair scheme: acc(r,c) = (even-k partial, odd-k partial);
//   acc += (s_k, s_k1) * (w_k,c , w_k1,c)   -- zero packing MOVs.
// 16 warps x 7 rows; lane = 4 cols. 3-stage cp.async ring.
// ---------------------------------------------------------------------------
__global__ void __launch_bounds__(THREADS, 1) gemm_kernel(float* __restrict__ out) {
    extern __shared__ char smem[];
    uint32_t ss = smem_u32(smem);
    uint32_t ws = ss + NSTAGE * SS_STAGE;

    int tid = threadIdx.x;
    int w   = tid >> 5;          // warp 0..15 -> rows [7w, 7w+7)
    int l   = tid & 31;          // lane -> cols [4l, 4l+4)
    int row0 = blockIdx.x * BM;

    unsigned long long acc[RPW][4];
#pragma unroll
    for (int r = 0; r < RPW; r++)
#pragma unroll
        for (int c = 0; c < 4; c++) acc[r][c] = 0ULL;

    auto issue_stage = [&](int stage, int c) {
        uint32_t sdst = ss + stage * SS_STAGE;
        uint32_t wdst = ws + stage * WS_STAGE;
        const char* wsrc = (const char*)g_Wp + (size_t)c * WS_STAGE;
#pragma unroll
        for (int i = 0; i < 2; i++) {
            int t = tid + i * THREADS;
            if (t < BM * 9) {
                int row = t / 9, qq = t - row * 9;
                int grow = row0 + row;
                if (grow >= N_ATOMS) grow = N_ATOMS - 1;   // clamp (discarded later)
                asm volatile("cp.async.ca.shared.global [%0], [%1], 16;"
                             :: "r"(sdst + row * SROW_B + qq * 16),
                                "l"((const char*)(g_S + (size_t)grow * KDIM) +
                                    c * (BK * 4) + qq * 16)
                             : "memory");
            }
        }
#pragma unroll
        for (int i = 0; i < 3; i++) {
            int t = tid + i * THREADS;
            if (t < WS_STAGE / 16) {
                asm volatile("cp.async.ca.shared.global [%0], [%1], 16;"
                             :: "r"(wdst + t * 16), "l"(wsrc + t * 16) : "memory");
            }
        }
        asm volatile("cp.async.commit_group;" ::: "memory");
    };

    issue_stage(0, 0);
    issue_stage(1, 1);
    asm volatile("cp.async.wait_group 1;" ::: "memory");
    __syncthreads();

    int st = 0;
    for (int c = 0; c < NITER; ++c) {
        bool more = (c + 2 < NITER);
        if (more) {
            int nst = st + 2; if (nst >= NSTAGE) nst -= NSTAGE;
            issue_stage(nst, c + 2);
        }

        uint32_t sa = ss + st * SS_STAGE + (w * RPW) * SROW_B;
        uint32_t wa = ws + st * WS_STAGE + l * 32;

#pragma unroll
        for (int kq = 0; kq < BK / 4; kq++) {      // 4 k = 2 kpairs per step
            // W: lane's 4 cols' (w_even, w_odd) pairs for both kpairs
            unsigned long long wv[2][4];
#pragma unroll
            for (int kp = 0; kp < 2; kp++) {
                uint32_t a = wa + (kq * 2 + kp) * (NPAD * 8);
                asm("ld.shared.v2.u64 {%0,%1}, [%2];"
                    : "=l"(wv[kp][0]), "=l"(wv[kp][1]) : "r"(a));
                asm("ld.shared.v2.u64 {%0,%1}, [%2];"
                    : "=l"(wv[kp][2]), "=l"(wv[kp][3]) : "r"(a + 16));
            }
#pragma unroll
            for (int r = 0; r < RPW; r++) {
                unsigned long long sA, sB;   // (s_k0,s_k1), (s_k2,s_k3) broadcast
                asm("ld.shared.v2.u64 {%0,%1}, [%2];"
                    : "=l"(sA), "=l"(sB) : "r"(sa + r * SROW_B + kq * 16));
#pragma unroll
                for (int cc = 0; cc < 4; cc++) {
                    asm volatile("fma.rn.f32x2 %0, %1, %2, %0;"
                                 : "+l"(acc[r][cc]) : "l"(sA), "l"(wv[0][cc]));
                    asm volatile("fma.rn.f32x2 %0, %1, %2, %0;"
                                 : "+l"(acc[r][cc]) : "l"(sB), "l"(wv[1][cc]));
                }
            }
        }

        if (more) asm volatile("cp.async.wait_group 1;" ::: "memory");
        else      asm volatile("cp.async.wait_group 0;" ::: "memory");
        __syncthreads();

        if (++st == NSTAGE) st = 0;
    }

    // epilogue: fold (even,odd) partials; rows 7w..7w+6, cols 4l..4l+3
    if (l * 4 < NH) {
#pragma unroll
        for (int r = 0; r < RPW; r++) {
            int row = row0 + w * RPW + r;
            if (row < N_ATOMS) {
                float v[4];
#pragma unroll
                for (int cc = 0; cc < 4; cc++) {
                    float lo, hi;
                    asm("mov.b64 {%0,%1}, %2;" : "=f"(lo), "=f"(hi) : "l"(acc[r][cc]));
                    v[cc] = lo + hi;
                }
                *(float4*)(out + (size_t)row * NH + l * 4) =
                    make_float4(v[0], v[1], v[2], v[3]);
            }
        }
    }
}

// ---------------------------------------------------------------------------
extern "C" void kernel_launch(void* const* d_in, const int* in_sizes, int n_in,
                              void* d_out, int out_size) {
    const float* pf  = (const float*)d_in[0];   // [64000, 8]
    const float* af  = (const float*)d_in[1];   // [16000, 100]
    const int*   a2p = (const int*)  d_in[2];   // [64000, 2]
    const float* W   = (const float*)d_in[3];   // [8, 10000]
    const float* b   = (const float*)d_in[4];   // [10000]
    float* out = (float*)d_out;                 // [16000, 100]

    void* cur_ptr = nullptr;
    cudaGetSymbolAddress(&cur_ptr, g_cursor);
    cudaFuncSetAttribute(gemm_kernel,
                         cudaFuncAttributeMaxDynamicSharedMemorySize, SMEM_TOTAL);

    prep_wp_kernel<<<((KDIM / 2) * 32 + 255) / 256, 256>>>(W, b);
    cudaMemsetAsync(cur_ptr, 0, N_ATOMS * sizeof(uint32_t));
    fill_kernel<<<(N_PAIRS + 255) / 256, 256>>>(a2p);
    gather_kernel<<<N_ATOMS / 10, 250>>>(pf, af, a2p);
    gemm_kernel<<<GRID, THREADS, SMEM_TOTAL>>>(out);
}